// round 1
// baseline (speedup 1.0000x reference)
#include <cuda_runtime.h>

// Problem constants (fixed by setup_inputs)
#define T_LEN 8192
#define H_HEADS 16
#define B_BATCH 2
#define P_DIM 64
#define N_DIM 64
#define BH (B_BATCH * H_HEADS)   // 32

#define K1_THREADS 256
#define ITEMS 32                 // K1_THREADS * ITEMS == T_LEN
#define THRESH 45.0f             // exp(-45) ~ 3e-20: contributions utterly negligible

#define KS 64                    // timesteps per block in state kernel
#define KT 16                    // timesteps per smem tile

// Scratch (allocation-free rule: device globals)
__device__ float g_w[BH * T_LEN];     // weights, laid out [bh][t]
__device__ int   g_tmin[BH];          // first timestep with non-negligible weight

// ---------------------------------------------------------------------------
// Kernel 1: per (b,h) reverse exclusive cumsum of A -> w[t] = exp(sum_{t'>t} a)
// Backward accumulation keeps the exponent small where weights matter.
// ---------------------------------------------------------------------------
__global__ void __launch_bounds__(K1_THREADS)
weights_kernel(const float* __restrict__ A) {
    int bh = blockIdx.x;
    int b = bh / H_HEADS, hh = bh % H_HEADS;
    int tid = threadIdx.x;

    __shared__ float s_tot[K1_THREADS];
    __shared__ float s_excl[K1_THREADS];
    __shared__ int   s_cut;
    if (tid == 0) s_cut = T_LEN;

    const float* Ab = A + (size_t)b * T_LEN * H_HEADS + hh;
    int u0 = tid * ITEMS;

    // Pass 1: per-thread totals over reversed index u = T-1-t
    float vals[ITEMS];
    float tot = 0.f;
#pragma unroll
    for (int i = 0; i < ITEMS; i++) {
        int t = T_LEN - 1 - (u0 + i);
        float a = Ab[(size_t)t * H_HEADS];
        vals[i] = a;
        tot += a;
    }
    s_tot[tid] = tot;
    __syncthreads();

    // Exclusive scan of per-thread totals (sequential; 256 adds, negligible)
    if (tid == 0) {
        float run = 0.f;
        for (int j = 0; j < K1_THREADS; j++) { s_excl[j] = run; run += s_tot[j]; }
    }
    __syncthreads();

    // Pass 2: emit weights, find cutoff (suffix sum is monotone nonincreasing
    // in u since a <= 0 by construction).
    float p = s_excl[tid];
    float* wb = g_w + (size_t)bh * T_LEN;
    int cand = T_LEN;
#pragma unroll
    for (int i = 0; i < ITEMS; i++) {
        int u = u0 + i;
        int t = T_LEN - 1 - u;
        wb[t] = expf(p);
        if (p < -THRESH && cand == T_LEN) cand = u;
        p += vals[i];
    }
    if (cand < T_LEN) atomicMin(&s_cut, cand);
    __syncthreads();
    if (tid == 0) g_tmin[bh] = T_LEN - s_cut;   // s_cut==T_LEN -> tmin = 0
}

// ---------------------------------------------------------------------------
// Kernel 2: per (b,h), per 64-timestep K-slice: S[p,n] += sum_t w_t X[t,p] B[t,n]
// Blocks whose slice is entirely below t_min exit immediately (~90%+ of grid).
// ---------------------------------------------------------------------------
__global__ void __launch_bounds__(256)
state_kernel(const float* __restrict__ X, const float* __restrict__ Bm,
             float* __restrict__ out) {
    int bh = blockIdx.y;
    int t0 = blockIdx.x * KS;
    if (t0 + KS <= g_tmin[bh]) return;   // all weights in this slice ~0

    int b = bh / H_HEADS, hh = bh % H_HEADS;
    int tid = threadIdx.x;

    __shared__ float sX[KT][P_DIM];
    __shared__ float sB[KT][N_DIM];

    int p0 = (tid >> 4) << 2;   // thread's 4 output rows
    int n0 = (tid & 15) << 2;   // thread's 4 output cols
    float acc[4][4] = {};

    const float* wb = g_w + (size_t)bh * T_LEN;

    // loader mapping: 256 threads -> 16 rows x 16 float4 per row
    int lrow = tid >> 4;
    int lcol = (tid & 15) << 2;

    for (int kt = 0; kt < KS; kt += KT) {
        int t = t0 + kt + lrow;
        size_t goff = (((size_t)b * T_LEN + t) * H_HEADS + hh) * P_DIM + lcol;
        float w = wb[t];
        float4 xv = *(const float4*)(X + goff);
        xv.x *= w; xv.y *= w; xv.z *= w; xv.w *= w;
        *(float4*)&sX[lrow][lcol] = xv;
        *(float4*)&sB[lrow][lcol] = *(const float4*)(Bm + goff);
        __syncthreads();

#pragma unroll
        for (int tt = 0; tt < KT; tt++) {
            float4 xr = *(const float4*)&sX[tt][p0];
            float4 br = *(const float4*)&sB[tt][n0];
            float xa[4] = {xr.x, xr.y, xr.z, xr.w};
            float ba[4] = {br.x, br.y, br.z, br.w};
#pragma unroll
            for (int i = 0; i < 4; i++)
#pragma unroll
                for (int j = 0; j < 4; j++)
                    acc[i][j] += xa[i] * ba[j];
        }
        __syncthreads();
    }

    float* ob = out + (size_t)bh * (P_DIM * N_DIM);
#pragma unroll
    for (int i = 0; i < 4; i++)
#pragma unroll
        for (int j = 0; j < 4; j++)
            atomicAdd(&ob[(p0 + i) * N_DIM + n0 + j], acc[i][j]);
}

// ---------------------------------------------------------------------------
extern "C" void kernel_launch(void* const* d_in, const int* in_sizes, int n_in,
                              void* d_out, int out_size) {
    const float* X = (const float*)d_in[0];
    const float* A = (const float*)d_in[1];
    const float* B = (const float*)d_in[2];
    float* out = (float*)d_out;

    cudaMemsetAsync(d_out, 0, (size_t)out_size * sizeof(float));
    weights_kernel<<<BH, K1_THREADS>>>(A);
    dim3 grid(T_LEN / KS, BH);
    state_kernel<<<grid, 256>>>(X, B, out);
}

// round 2
// speedup vs baseline: 1.6936x; 1.6936x over previous
#include <cuda_runtime.h>

// Problem constants (fixed by setup_inputs)
#define T_LEN 8192
#define H_HEADS 16
#define B_BATCH 2
#define P_DIM 64
#define N_DIM 64
#define BH (B_BATCH * H_HEADS)   // 32

#define KS 32                    // timesteps per state block
#define NSLICE (T_LEN / KS)      // 256
#define THRESH 45.0f             // exp(-45) ~ 3e-20: utterly negligible

// Scratch (allocation-free rule: device globals)
__device__ float g_tail[BH * NSLICE];   // suffix sum of A beyond each slice

// ---------------------------------------------------------------------------
// Prep: per (b,h): chunk sums of A per 32-step slice -> suffix tails.
// Also zeroes the output (replaces cudaMemsetAsync node).
// grid = BH, block = NSLICE(=256) threads; thread j owns slice j.
// ---------------------------------------------------------------------------
__global__ void __launch_bounds__(NSLICE)
prep_kernel(const float* __restrict__ A, float* __restrict__ out) {
    int bh = blockIdx.x;
    int b = bh / H_HEADS, hh = bh % H_HEADS;
    int tid = threadIdx.x;

    __shared__ float s_chunk[NSLICE];

    const float* Ab = A + (size_t)b * T_LEN * H_HEADS + hh;
    int t0 = tid * KS;
    float s = 0.f;
#pragma unroll 8
    for (int k = 0; k < KS; k++)
        s += Ab[(size_t)(t0 + k) * H_HEADS];
    s_chunk[tid] = s;

    // zero the output region for this bh (before any state block runs)
    float* ob = out + (size_t)bh * (P_DIM * N_DIM);
#pragma unroll
    for (int i = 0; i < (P_DIM * N_DIM) / NSLICE; i++)
        ob[tid + i * NSLICE] = 0.f;

    __syncthreads();
    float tail = 0.f;
    for (int j = tid + 1; j < NSLICE; j++) tail += s_chunk[j];
    g_tail[bh * NSLICE + tid] = tail;
}

// ---------------------------------------------------------------------------
// State: per (b,h) per 32-step slice: S[p,n] += sum_t w_t X[t,p] B[t,n]
//   w_t = exp(tail + suffix-sum of a within the slice)
// 128 threads, 8x4 register tile per thread, vector red epilogue.
// Inactive slices (tail < -45) exit after one load.
// ---------------------------------------------------------------------------
__global__ void __launch_bounds__(128)
state_kernel(const float* __restrict__ X, const float* __restrict__ Bm,
             const float* __restrict__ A, float* __restrict__ out) {
    int bh = blockIdx.y;
    int slice = blockIdx.x;
    float tail = g_tail[bh * NSLICE + slice];
    if (tail < -THRESH) return;

    int b = bh / H_HEADS, hh = bh % H_HEADS;
    int tid = threadIdx.x;
    int t0 = slice * KS;

    __shared__ float s_a[KS];
    __shared__ float s_wt[KS];
    __shared__ float sX[KS][P_DIM];
    __shared__ float sB[KS][N_DIM];

    // slice's A values
    if (tid < KS)
        s_a[tid] = A[((size_t)b * T_LEN + t0 + tid) * H_HEADS + hh];

    // issue gmem tile loads into registers (overlaps the weight computation)
    int lrow = tid >> 4;          // 0..7
    int lcol = (tid & 15) << 2;   // 0..60
    float4 xr[4], br[4];
#pragma unroll
    for (int k = 0; k < 4; k++) {
        int r = k * 8 + lrow;
        size_t goff = (((size_t)b * T_LEN + t0 + r) * H_HEADS + hh) * P_DIM + lcol;
        xr[k] = *(const float4*)(X + goff);
        br[k] = *(const float4*)(Bm + goff);
    }
    __syncthreads();   // s_a visible

    // weights: w[t] = exp(tail + sum_{t'>t within slice} a[t'])
    if (tid < KS) {
        float s = tail;
        for (int j = tid + 1; j < KS; j++) s += s_a[j];
        s_wt[tid] = expf(s);
    }
    __syncthreads();   // s_wt visible

    // stage tiles (X pre-scaled by weight)
#pragma unroll
    for (int k = 0; k < 4; k++) {
        int r = k * 8 + lrow;
        float w = s_wt[r];
        float4 xv = xr[k];
        xv.x *= w; xv.y *= w; xv.z *= w; xv.w *= w;
        *(float4*)&sX[r][lcol] = xv;
        *(float4*)&sB[r][lcol] = br[k];
    }
    __syncthreads();

    // 8x4 register tile
    int p0 = (tid >> 4) << 3;   // 0..56
    int n0 = (tid & 15) << 2;   // 0..60
    float acc[8][4] = {};

#pragma unroll 8
    for (int tt = 0; tt < KS; tt++) {
        float4 x0 = *(const float4*)&sX[tt][p0];
        float4 x1 = *(const float4*)&sX[tt][p0 + 4];
        float4 bv = *(const float4*)&sB[tt][n0];
        float xa[8] = {x0.x, x0.y, x0.z, x0.w, x1.x, x1.y, x1.z, x1.w};
        float ba[4] = {bv.x, bv.y, bv.z, bv.w};
#pragma unroll
        for (int i = 0; i < 8; i++)
#pragma unroll
            for (int j = 0; j < 4; j++)
                acc[i][j] += xa[i] * ba[j];
    }

    // vector reduction epilogue: 8 red.v4 per thread
    float* ob = out + (size_t)bh * (P_DIM * N_DIM);
#pragma unroll
    for (int i = 0; i < 8; i++) {
        float* p = &ob[(p0 + i) * N_DIM + n0];
        asm volatile("red.global.add.v4.f32 [%0], {%1, %2, %3, %4};"
                     :: "l"(p), "f"(acc[i][0]), "f"(acc[i][1]),
                        "f"(acc[i][2]), "f"(acc[i][3])
                     : "memory");
    }
}

// ---------------------------------------------------------------------------
extern "C" void kernel_launch(void* const* d_in, const int* in_sizes, int n_in,
                              void* d_out, int out_size) {
    const float* X = (const float*)d_in[0];
    const float* A = (const float*)d_in[1];
    const float* B = (const float*)d_in[2];
    float* out = (float*)d_out;

    prep_kernel<<<BH, NSLICE>>>(A, out);
    dim3 grid(NSLICE, BH);
    state_kernel<<<grid, 128>>>(X, B, A, out);
}

// round 4
// speedup vs baseline: 1.8767x; 1.1081x over previous
#include <cuda_runtime.h>

// Problem constants (fixed by setup_inputs)
#define T_LEN 8192
#define H_HEADS 16
#define B_BATCH 2
#define P_DIM 64
#define N_DIM 64
#define BH (B_BATCH * H_HEADS)   // 32

#define KS 32                    // timesteps per state slice
#define NSLICE (T_LEN / KS)      // 256
#define PHALF 32                 // p-split: each state block owns 32 of 64 p-rows
#define THRESH 45.0f             // exp(-45) ~ 3e-20: utterly negligible

#define TSTEP 128                // t-rows per prep-A block

// Scratch (allocation-free rule: device globals)
__device__ float g_chunk[BH * NSLICE];  // per-slice sums of A
__device__ float g_tail[BH * NSLICE];   // suffix sum of A beyond each slice

// ---------------------------------------------------------------------------
// Prep A: coalesced chunk sums. A is [b, T, h] so (t, h) is contiguous.
// grid = (T/128, B), 256 threads. Each block: 128 t x 16 h tile -> 4 chunk
// sums per h (32-step chunks).
// ---------------------------------------------------------------------------
__global__ void __launch_bounds__(256)
prepA_kernel(const float* __restrict__ A) {
    int b = blockIdx.y;
    int t0 = blockIdx.x * TSTEP;
    int tid = threadIdx.x;

    __shared__ float s_tile[TSTEP * 17];   // [t][h], padded row=17 (scalar access only)
    __shared__ float s_part[256];

    const float* Ab = A + ((size_t)b * T_LEN + t0) * H_HEADS;
#pragma unroll
    for (int i = 0; i < (TSTEP * H_HEADS) / 256; i++) {
        int idx = tid + i * 256;           // contiguous gmem
        int t = idx >> 4, h = idx & 15;
        s_tile[t * 17 + h] = Ab[idx];
    }
    __syncthreads();

    // thread = (chunk c: 2b, sub: 2b, h: 4b); each sums 8 t-values
    int c   = tid >> 6;
    int sub = (tid >> 4) & 3;
    int h   = tid & 15;
    float s = 0.f;
#pragma unroll
    for (int r = 0; r < 8; r++)
        s += s_tile[(c * 32 + sub * 8 + r) * 17 + h];
    s_part[tid] = s;
    __syncthreads();

    if (sub == 0) {
        float tot = s_part[tid] + s_part[tid + 16] + s_part[tid + 32] + s_part[tid + 48];
        int slice = blockIdx.x * 4 + c;
        int bh = b * H_HEADS + h;
        g_chunk[bh * NSLICE + slice] = tot;
    }
}

// ---------------------------------------------------------------------------
// Prep B: per bh, suffix-scan the 256 chunk sums -> tails. Also zero output.
// grid = BH, 256 threads (thread j owns slice j).
// ---------------------------------------------------------------------------
__global__ void __launch_bounds__(NSLICE)
prepB_kernel(float* __restrict__ out) {
    int bh = blockIdx.x;
    int tid = threadIdx.x;

    __shared__ float s[NSLICE];
    s[tid] = g_chunk[bh * NSLICE + tid];

    // zero this bh's output tile
    float* ob = out + (size_t)bh * (P_DIM * N_DIM);
#pragma unroll
    for (int i = 0; i < (P_DIM * N_DIM) / NSLICE; i++)
        ob[tid + i * NSLICE] = 0.f;

    __syncthreads();
    // inclusive suffix scan (Hillis-Steele)
#pragma unroll
    for (int off = 1; off < NSLICE; off <<= 1) {
        float add = (tid + off < NSLICE) ? s[tid + off] : 0.f;
        __syncthreads();
        s[tid] += add;
        __syncthreads();
    }
    // tail (exclusive) = inclusive suffix at tid+1
    g_tail[bh * NSLICE + tid] = (tid + 1 < NSLICE) ? s[tid + 1] : 0.f;
}

// ---------------------------------------------------------------------------
// State: per (slice, bh, p-half): S[p,n] += sum_t w_t X[t,p] B[t,n]
// 128 threads, 4x4 register tile over a 32x64 output half.
// NOTE: smem rows UNPADDED — float4 LDS/STS require 16B alignment.
// ---------------------------------------------------------------------------
__global__ void __launch_bounds__(128)
state_kernel(const float* __restrict__ X, const float* __restrict__ Bm,
             const float* __restrict__ A, float* __restrict__ out) {
    int bh = blockIdx.y;
    int slice = blockIdx.x;
    float tail = g_tail[bh * NSLICE + slice];
    if (tail < -THRESH) return;

    int b = bh / H_HEADS, hh = bh % H_HEADS;
    int tid = threadIdx.x;
    int t0 = slice * KS;
    int ph = blockIdx.z * PHALF;

    __shared__ float s_a[KS];
    __shared__ float s_wt[KS];
    __shared__ float sX[KS][PHALF];
    __shared__ float sB[KS][N_DIM];

    if (tid < KS)
        s_a[tid] = A[((size_t)b * T_LEN + t0 + tid) * H_HEADS + hh];

    // gmem tile loads into registers (overlap with weight computation)
    // X half-tile: 32t x 32p; thread: rows (tid>>3)+16k, col (tid&7)*4
    int xrow = tid >> 3, xcol = (tid & 7) << 2;
    float4 xr[2];
#pragma unroll
    for (int k = 0; k < 2; k++) {
        int r = xrow + 16 * k;
        xr[k] = *(const float4*)(X + (((size_t)b * T_LEN + t0 + r) * H_HEADS + hh) * P_DIM
                                   + ph + xcol);
    }
    // B tile: 32t x 64n; thread: rows (tid>>4)+8k, col (tid&15)*4
    int brow = tid >> 4, bcol = (tid & 15) << 2;
    float4 br[4];
#pragma unroll
    for (int k = 0; k < 4; k++) {
        int r = brow + 8 * k;
        br[k] = *(const float4*)(Bm + (((size_t)b * T_LEN + t0 + r) * H_HEADS + hh) * P_DIM
                                    + bcol);
    }
    __syncthreads();   // s_a visible

    // w[t] = exp(tail + sum_{t'>t in slice} a[t'])
    if (tid < KS) {
        float s = tail;
        for (int j = tid + 1; j < KS; j++) s += s_a[j];
        s_wt[tid] = expf(s);
    }
    __syncthreads();   // s_wt visible

    // stage tiles (X pre-scaled by weight)
#pragma unroll
    for (int k = 0; k < 2; k++) {
        int r = xrow + 16 * k;
        float w = s_wt[r];
        float4 xv = xr[k];
        xv.x *= w; xv.y *= w; xv.z *= w; xv.w *= w;
        *(float4*)&sX[r][xcol] = xv;
    }
#pragma unroll
    for (int k = 0; k < 4; k++)
        *(float4*)&sB[brow + 8 * k][bcol] = br[k];
    __syncthreads();

    // 4x4 register tile over 32x64
    int p0 = (tid >> 4) << 2;   // 0..28
    int n0 = (tid & 15) << 2;   // 0..60
    float acc[4][4] = {};

#pragma unroll
    for (int tt = 0; tt < KS; tt++) {
        float4 xv = *(const float4*)&sX[tt][p0];
        float4 bv = *(const float4*)&sB[tt][n0];
        float xa[4] = {xv.x, xv.y, xv.z, xv.w};
        float ba[4] = {bv.x, bv.y, bv.z, bv.w};
#pragma unroll
        for (int i = 0; i < 4; i++)
#pragma unroll
            for (int j = 0; j < 4; j++)
                acc[i][j] += xa[i] * ba[j];
    }

    // vector reduction epilogue (16B-aligned: n0 multiple of 4 floats, row 256B)
    float* ob = out + (size_t)bh * (P_DIM * N_DIM);
#pragma unroll
    for (int i = 0; i < 4; i++) {
        float* p = &ob[(ph + p0 + i) * N_DIM + n0];
        asm volatile("red.global.add.v4.f32 [%0], {%1, %2, %3, %4};"
                     :: "l"(p), "f"(acc[i][0]), "f"(acc[i][1]),
                        "f"(acc[i][2]), "f"(acc[i][3])
                     : "memory");
    }
}

// ---------------------------------------------------------------------------
extern "C" void kernel_launch(void* const* d_in, const int* in_sizes, int n_in,
                              void* d_out, int out_size) {
    const float* X = (const float*)d_in[0];
    const float* A = (const float*)d_in[1];
    const float* B = (const float*)d_in[2];
    float* out = (float*)d_out;

    dim3 gA(T_LEN / TSTEP, B_BATCH);
    prepA_kernel<<<gA, 256>>>(A);
    prepB_kernel<<<BH, NSLICE>>>(out);
    dim3 gS(NSLICE, BH, 2);
    state_kernel<<<gS, 128>>>(X, B, A, out);
}